// round 9
// baseline (speedup 1.0000x reference)
#include <cuda_runtime.h>
#include <cuda_bf16.h>
#include <cstdint>

// Flash attention via mma.sync (HMMA bf16), hi/lo split precision, fp32 accum.
// B=4,H=16,L=2048,D=128. scale=1. Q pre-scaled by log2(e); p = 2^(s-28.854).
// 512 threads / 16 warps: warps split (row-group, half). P staged in smem.
// V double-buffered, K single-buffered (prefetched after post-S barrier).

#define L_SEQ   2048
#define DH      128
#define NHEADS  64
#define BM      128
#define BN      64
#define NTILES  (L_SEQ/BN)
#define NTH     512
#define TOT     (NHEADS*L_SEQ*DH)

__device__ __nv_bfloat16 g_Qh[TOT], g_Ql[TOT], g_Kh[TOT], g_Kl[TOT];
__device__ __nv_bfloat16 g_VTh[TOT], g_VTl[TOT];   // [head][d][l]

// smem layout (bytes)
#define QSTR 272
#define VSTR 144
#define PSTR 144
#define SQH  0u
#define SQL  34816u
#define SKH  69632u
#define SKL  87040u
#define SV0  104448u          // VH +0 (18432) | VL +18432 (18432)
#define SV1  141312u
#define VBUFSZ 36864u
#define VL_OFF 18432u
#define SPH  178176u
#define SPL  196608u
#define SMEM_TOTAL 215040u

__device__ __forceinline__ uint32_t smem_u32(const void* p) {
    uint32_t a;
    asm("{ .reg .u64 t; cvta.to.shared.u64 t, %1; cvt.u32.u64 %0, t; }" : "=r"(a) : "l"(p));
    return a;
}
__device__ __forceinline__ void ldsm4(uint32_t r[4], uint32_t addr) {
    asm volatile("ldmatrix.sync.aligned.m8n8.x4.shared.b16 {%0,%1,%2,%3}, [%4];"
                 : "=r"(r[0]), "=r"(r[1]), "=r"(r[2]), "=r"(r[3]) : "r"(addr));
}
__device__ __forceinline__ void mma16816(float c[4], const uint32_t a[4],
                                         uint32_t b0, uint32_t b1) {
    asm volatile("mma.sync.aligned.m16n8k16.row.col.f32.bf16.bf16.f32 "
                 "{%0,%1,%2,%3},{%4,%5,%6,%7},{%8,%9},{%0,%1,%2,%3};"
                 : "+f"(c[0]), "+f"(c[1]), "+f"(c[2]), "+f"(c[3])
                 : "r"(a[0]), "r"(a[1]), "r"(a[2]), "r"(a[3]), "r"(b0), "r"(b1));
}
__device__ __forceinline__ uint32_t packbf2(float x, float y) {
    __nv_bfloat162 t = __floats2bfloat162_rn(x, y);
    return *reinterpret_cast<uint32_t*>(&t);
}
__device__ __forceinline__ float ex2(float x) {
    float y; asm("ex2.approx.f32 %0, %1;" : "=f"(y) : "f"(x)); return y;
}
__device__ __forceinline__ void cpa16(uint32_t dst, const void* src) {
    asm volatile("cp.async.cg.shared.global [%0], [%1], 16;" :: "r"(dst), "l"(src));
}
#define CPA_COMMIT() asm volatile("cp.async.commit_group;" ::: "memory")
#define CPA_WAIT0()  asm volatile("cp.async.wait_group 0;" ::: "memory")

// ---------------- pre-pass: split Q/K into hi/lo bf16 (Q scaled by log2 e) ----------------
__global__ void split_kernel(const float4* __restrict__ in, int which) {
    __nv_bfloat162* hi = (__nv_bfloat162*)(which ? g_Kh : g_Qh);
    __nv_bfloat162* lo = (__nv_bfloat162*)(which ? g_Kl : g_Ql);
    const float sc = which ? 1.0f : 1.4426950408889634f;
    int n4 = TOT / 4;
    for (int i = blockIdx.x * blockDim.x + threadIdx.x; i < n4; i += gridDim.x * blockDim.x) {
        float4 x = in[i];
        x.x *= sc; x.y *= sc; x.z *= sc; x.w *= sc;
        __nv_bfloat16 hx = __float2bfloat16(x.x), hy = __float2bfloat16(x.y);
        __nv_bfloat16 hz = __float2bfloat16(x.z), hw = __float2bfloat16(x.w);
        hi[2*i]   = __halves2bfloat162(hx, hy);
        hi[2*i+1] = __halves2bfloat162(hz, hw);
        lo[2*i]   = __halves2bfloat162(__float2bfloat16(x.x - __bfloat162float(hx)),
                                       __float2bfloat16(x.y - __bfloat162float(hy)));
        lo[2*i+1] = __halves2bfloat162(__float2bfloat16(x.z - __bfloat162float(hz)),
                                       __float2bfloat16(x.w - __bfloat162float(hw)));
    }
}

// ---------------- pre-pass: transpose V -> [head][d][l], split hi/lo ----------------
__global__ void vtrans_kernel(const float* __restrict__ V) {
    __shared__ float s[32][33];
    int head = blockIdx.z, lt = blockIdx.x, dt = blockIdx.y;
    const float* base = V + (size_t)head * L_SEQ * DH + (size_t)lt * 32 * DH + dt * 32;
    int t = threadIdx.x;
    int r = t >> 3, c4 = t & 7;
    float4 v = *(const float4*)(base + r * DH + c4 * 4);
    s[r][c4*4+0] = v.x; s[r][c4*4+1] = v.y; s[r][c4*4+2] = v.z; s[r][c4*4+3] = v.w;
    __syncthreads();
    #pragma unroll
    for (int p = 0; p < 2; p++) {
        int idx = t + p * 256;
        int dr = idx >> 4, j = idx & 15;
        float a = s[2*j][dr], b = s[2*j+1][dr];
        __nv_bfloat16 ah = __float2bfloat16(a), bh = __float2bfloat16(b);
        size_t o = (size_t)head * DH * L_SEQ + (size_t)(dt*32 + dr) * L_SEQ + lt*32 + 2*j;
        *(__nv_bfloat162*)(g_VTh + o) = __halves2bfloat162(ah, bh);
        *(__nv_bfloat162*)(g_VTl + o) = __halves2bfloat162(
            __float2bfloat16(a - __bfloat162float(ah)),
            __float2bfloat16(b - __bfloat162float(bh)));
    }
}

// ---------------- main attention kernel ----------------
__global__ __launch_bounds__(NTH, 1)
void fa_mma_kernel(float* __restrict__ O) {
    extern __shared__ char smp[];
    const uint32_t sb = smem_u32(smp);

    const int tid = threadIdx.x, wid = tid >> 5, lane = tid & 31;
    const int rg = wid & 7, ch = wid >> 3;
    const int head = blockIdx.y, q0 = blockIdx.x * BM;
    const size_t hb = (size_t)head * L_SEQ * DH;

    const __nv_bfloat16* khg = g_Kh + hb;
    const __nv_bfloat16* klg = g_Kl + hb;
    const __nv_bfloat16* vhg = g_VTh + (size_t)head * DH * L_SEQ;
    const __nv_bfloat16* vlg = g_VTl + (size_t)head * DH * L_SEQ;

    // ---- prefetch tile 0: K into single K buf, V into V buf 0 ----
    {
        #pragma unroll
        for (int i = 0; i < 4; i++) {
            int idx = tid + i * NTH;
            int arr = idx >> 10, rem = idx & 1023;
            int r = rem >> 4, c = rem & 15;
            cpa16(sb + (arr ? SKL : SKH) + r * QSTR + c * 16,
                  (arr ? klg : khg) + (size_t)r * DH + c * 8);
        }
        #pragma unroll
        for (int i = 0; i < 4; i++) {
            int idx = tid + i * NTH;
            int arr = idx >> 10, rem = idx & 1023;
            int r = rem >> 3, c = rem & 7;
            cpa16(sb + SV0 + (arr ? VL_OFF : 0u) + r * VSTR + c * 16,
                  (arr ? vlg : vhg) + (size_t)r * L_SEQ + c * 8);
        }
        CPA_COMMIT();
    }

    // ---- load Q tile (plain LDG/STS, once) ----
    {
        const __nv_bfloat16* qh = g_Qh + hb + (size_t)q0 * DH;
        const __nv_bfloat16* ql = g_Ql + hb + (size_t)q0 * DH;
        #pragma unroll
        for (int i = 0; i < 8; i++) {
            int idx = tid + i * NTH;
            int arr = idx >> 11, rem = idx & 2047;
            int r = rem >> 4, c = rem & 15;
            uint4 v = *(const uint4*)((arr ? ql : qh) + r * DH + c * 8);
            *(uint4*)(smp + (arr ? SQL : SQH) + r * QSTR + c * 16) = v;
        }
    }

    // ---- fragment addressing ----
    // A-frag rows (Q and P): 16 rows of this row-group
    const int arow = rg * 16 + (lane & 7) + ((lane >> 3) & 1) * 8;
    const uint32_t acolb = ((lane >> 4) & 1) * 16;
    const uint32_t qaH = sb + SQH + arow * QSTR + acolb;
    const uint32_t qaL = sb + SQL + arow * QSTR + acolb;
    const uint32_t paH = sb + SPH + arow * PSTR + acolb;
    const uint32_t paL = sb + SPL + arow * PSTR + acolb;
    // B-frag rows: K rows ch*32 + np2*16 + pat ; V rows ch*64 + np*16 + pat
    const int bpat = (lane & 7) + ((lane >> 4) & 1) * 8;
    const uint32_t bcolb = ((lane >> 3) & 1) * 16;
    const uint32_t kfragH = sb + SKH + (ch * 32 + bpat) * QSTR + bcolb;
    const uint32_t kfragL = sb + SKL + (ch * 32 + bpat) * QSTR + bcolb;
    const uint32_t vfrag  = (ch * 64 + bpat) * VSTR + bcolb;

    // P store addressing (per-lane): rows r_lo, r_lo+8; col pair (lane&3)*2
    const int prow = rg * 16 + (lane >> 2);
    const uint32_t pstW = prow * PSTR + (ch * 32) * 2 + (lane & 3) * 4;

    float oc[8][4];
    #pragma unroll
    for (int i = 0; i < 8; i++)
        #pragma unroll
        for (int j = 0; j < 4; j++) oc[i][j] = 0.0f;
    float psum0 = 0.0f, psum1 = 0.0f;

    #pragma unroll 1
    for (int t = 0; t < NTILES; t++) {
        CPA_WAIT0();
        __syncthreads();   // K(t),V(t) ready; PV(t-1) reads of P and V done

        // ---- prefetch V(t+1) into other V buffer ----
        if (t + 1 < NTILES) {
            const uint32_t vb = sb + (((t + 1) & 1) ? SV1 : SV0);
            const int vo = (t + 1) * BN;
            #pragma unroll
            for (int i = 0; i < 4; i++) {
                int idx = tid + i * NTH;
                int arr = idx >> 10, rem = idx & 1023;
                int r = rem >> 3, c = rem & 7;
                cpa16(vb + (arr ? VL_OFF : 0u) + r * VSTR + c * 16,
                      (arr ? vlg : vhg) + (size_t)r * L_SEQ + vo + c * 8);
            }
        }

        // ---- S = Qh*Kh + Qh*Kl + Ql*Kh : 16 rows x 32 cols per warp ----
        float sc[4][4];
        #pragma unroll
        for (int i = 0; i < 4; i++)
            #pragma unroll
            for (int j = 0; j < 4; j++) sc[i][j] = 0.0f;

        #pragma unroll
        for (int kk = 0; kk < 8; kk++) {
            uint32_t aH[4], aL[4];
            ldsm4(aH, qaH + kk * 32);
            ldsm4(aL, qaL + kk * 32);
            #pragma unroll
            for (int np = 0; np < 2; np++) {
                uint32_t bH[4], bL[4];
                ldsm4(bH, kfragH + np * (16 * QSTR) + kk * 32);
                ldsm4(bL, kfragL + np * (16 * QSTR) + kk * 32);
                mma16816(sc[np*2],   aH, bH[0], bH[1]);
                mma16816(sc[np*2],   aH, bL[0], bL[1]);
                mma16816(sc[np*2],   aL, bH[0], bH[1]);
                mma16816(sc[np*2+1], aH, bH[2], bH[3]);
                mma16816(sc[np*2+1], aH, bL[2], bL[3]);
                mma16816(sc[np*2+1], aL, bH[2], bH[3]);
            }
        }

        // ---- p = 2^(s-28.854); split hi/lo into P smem; accumulate psum ----
        #pragma unroll
        for (int nt = 0; nt < 4; nt++) {
            float p0 = ex2(sc[nt][0] - 28.853900817779268f);
            float p1 = ex2(sc[nt][1] - 28.853900817779268f);
            float p2 = ex2(sc[nt][2] - 28.853900817779268f);
            float p3 = ex2(sc[nt][3] - 28.853900817779268f);
            psum0 += p0 + p1;
            psum1 += p2 + p3;
            uint32_t h01 = packbf2(p0, p1), h23 = packbf2(p2, p3);
            __nv_bfloat162 b01 = *(__nv_bfloat162*)&h01;
            __nv_bfloat162 b23 = *(__nv_bfloat162*)&h23;
            uint32_t l01 = packbf2(p0 - __bfloat162float(b01.x), p1 - __bfloat162float(b01.y));
            uint32_t l23 = packbf2(p2 - __bfloat162float(b23.x), p3 - __bfloat162float(b23.y));
            uint32_t cw = pstW + nt * 16;            // nt = np2*2+nh -> col offset nt*8 elems
            *(uint32_t*)(smp + SPH + cw)            = h01;
            *(uint32_t*)(smp + SPH + cw + 8*PSTR)   = h23;
            *(uint32_t*)(smp + SPL + cw)            = l01;
            *(uint32_t*)(smp + SPL + cw + 8*PSTR)   = l23;
        }
        __syncthreads();   // P visible; all warps done reading K(t)

        // ---- prefetch K(t+1) into the single K buffer ----
        if (t + 1 < NTILES) {
            const size_t ko = (size_t)(t + 1) * BN * DH;
            #pragma unroll
            for (int i = 0; i < 4; i++) {
                int idx = tid + i * NTH;
                int arr = idx >> 10, rem = idx & 1023;
                int r = rem >> 4, c = rem & 15;
                cpa16(sb + (arr ? SKL : SKH) + r * QSTR + c * 16,
                      (arr ? klg : khg) + ko + (size_t)r * DH + c * 8);
            }
        }
        CPA_COMMIT();

        // ---- O += Ph*Vh + Ph*Vl + Pl*Vh : 16 rows x 64 d-cols per warp ----
        const uint32_t vbH = sb + ((t & 1) ? SV1 : SV0) + vfrag;
        const uint32_t vbL = vbH + VL_OFF;
        #pragma unroll
        for (int kk = 0; kk < 4; kk++) {
            uint32_t aPh[4], aPl[4];
            ldsm4(aPh, paH + kk * 32);
            ldsm4(aPl, paL + kk * 32);
            #pragma unroll
            for (int np = 0; np < 4; np++) {
                uint32_t bH[4], bL[4];
                ldsm4(bH, vbH + np * (16 * VSTR) + kk * 32);
                ldsm4(bL, vbL + np * (16 * VSTR) + kk * 32);
                mma16816(oc[np*2],   aPh, bH[0], bH[1]);
                mma16816(oc[np*2],   aPh, bL[0], bL[1]);
                mma16816(oc[np*2],   aPl, bH[0], bH[1]);
                mma16816(oc[np*2+1], aPh, bH[2], bH[3]);
                mma16816(oc[np*2+1], aPh, bL[2], bL[3]);
                mma16816(oc[np*2+1], aPl, bH[2], bH[3]);
            }
        }
    }

    // ---- psum: quad reduce, then cross-half (ch0+ch1) via smem ----
    psum0 += __shfl_xor_sync(0xffffffffu, psum0, 1);
    psum0 += __shfl_xor_sync(0xffffffffu, psum0, 2);
    psum1 += __shfl_xor_sync(0xffffffffu, psum1, 1);
    psum1 += __shfl_xor_sync(0xffffffffu, psum1, 2);
    __syncthreads();   // all PV reads of P smem done before reuse
    if ((lane & 3) == 0) {
        *(float*)(smp + SPH + (ch * 128 + prow) * 4)     = psum0;
        *(float*)(smp + SPH + (ch * 128 + prow + 8) * 4) = psum1;
    }
    __syncthreads();
    float inv0 = 1.0f / (*(float*)(smp + SPH + prow * 4)
                       + *(float*)(smp + SPH + (128 + prow) * 4));
    float inv1 = 1.0f / (*(float*)(smp + SPH + (prow + 8) * 4)
                       + *(float*)(smp + SPH + (128 + prow + 8) * 4));

    // ---- write O: rows prow, prow+8; d-cols ch*64 + np*16 + nh*8 + (lane&3)*2 ----
    float* Op0 = O + hb + (size_t)(q0 + prow) * DH + ch * 64 + (lane & 3) * 2;
    float* Op1 = Op0 + 8 * DH;
    #pragma unroll
    for (int nt = 0; nt < 8; nt++) {
        int cofs = (nt >> 1) * 16 + (nt & 1) * 8;
        *(float2*)(Op0 + cofs) = make_float2(oc[nt][0] * inv0, oc[nt][1] * inv0);
        *(float2*)(Op1 + cofs) = make_float2(oc[nt][2] * inv1, oc[nt][3] * inv1);
    }
}

extern "C" void kernel_launch(void* const* d_in, const int* in_sizes, int n_in,
                              void* d_out, int out_size) {
    const float* Q = (const float*)d_in[0];
    const float* K = (const float*)d_in[1];
    const float* V = (const float*)d_in[2];
    float* O = (float*)d_out;

    split_kernel<<<8192, 256>>>((const float4*)Q, 0);
    split_kernel<<<8192, 256>>>((const float4*)K, 1);
    vtrans_kernel<<<dim3(L_SEQ / 32, DH / 32, NHEADS), 256>>>(V);

    cudaFuncSetAttribute(fa_mma_kernel, cudaFuncAttributeMaxDynamicSharedMemorySize,
                         (int)SMEM_TOTAL);
    fa_mma_kernel<<<dim3(L_SEQ / BM, NHEADS), NTH, SMEM_TOTAL>>>(O);
}

// round 15
// speedup vs baseline: 1.2133x; 1.2133x over previous
#include <cuda_runtime.h>
#include <cuda_fp16.h>
#include <cstdint>

// Flash attention via mma.sync (HMMA fp16), hi/lo split precision, fp32 accum.
// B=4,H=16,L=2048,D=128. scale=1. Q pre-scaled by log2(e).
// Online softmax (per-row running max in log2 domain), p = 2^(s-m) in (0,1]
// -> all operands fp16. PV = (Ph+Pl)*Vh (V fp16 hi only; err ~2.1e-4 calibrated).
// cp.async double-buffered K/V.

#define L_SEQ   2048
#define DH      128
#define NHEADS  64
#define BM      128
#define BN      64
#define NTILES  (L_SEQ/BN)
#define NTH     256
#define TOT     (NHEADS*L_SEQ*DH)

__device__ __half g_Qh[TOT], g_Ql[TOT], g_Kh[TOT], g_Kl[TOT];
__device__ __half g_VTh[TOT];   // [head][d][l]

// smem layout (bytes)
#define QSTR 272
#define VSTR 144
#define SQH   0u
#define SQL   34816u
#define KBUF0 69632u          // KH 17408 | KL 17408
#define KBUFSZ 34816u
#define KL_OFF 17408u
#define VBUF0 139264u         // VH only, 18432
#define VBUFSZ 18432u
#define SMEM_TOTAL 176128u

__device__ __forceinline__ uint32_t smem_u32(const void* p) {
    uint32_t a;
    asm("{ .reg .u64 t; cvta.to.shared.u64 t, %1; cvt.u32.u64 %0, t; }" : "=r"(a) : "l"(p));
    return a;
}
__device__ __forceinline__ void ldsm4(uint32_t r[4], uint32_t addr) {
    asm volatile("ldmatrix.sync.aligned.m8n8.x4.shared.b16 {%0,%1,%2,%3}, [%4];"
                 : "=r"(r[0]), "=r"(r[1]), "=r"(r[2]), "=r"(r[3]) : "r"(addr));
}
__device__ __forceinline__ void mma16816(float c[4], const uint32_t a[4],
                                         uint32_t b0, uint32_t b1) {
    asm volatile("mma.sync.aligned.m16n8k16.row.col.f32.f16.f16.f32 "
                 "{%0,%1,%2,%3},{%4,%5,%6,%7},{%8,%9},{%0,%1,%2,%3};"
                 : "+f"(c[0]), "+f"(c[1]), "+f"(c[2]), "+f"(c[3])
                 : "r"(a[0]), "r"(a[1]), "r"(a[2]), "r"(a[3]), "r"(b0), "r"(b1));
}
__device__ __forceinline__ uint32_t packh2(float x, float y) {
    __half2 t = __floats2half2_rn(x, y);
    return *reinterpret_cast<uint32_t*>(&t);
}
__device__ __forceinline__ float ex2(float x) {
    float y; asm("ex2.approx.f32 %0, %1;" : "=f"(y) : "f"(x)); return y;
}
__device__ __forceinline__ void cpa16(uint32_t dst, const void* src) {
    asm volatile("cp.async.cg.shared.global [%0], [%1], 16;" :: "r"(dst), "l"(src));
}
#define CPA_COMMIT() asm volatile("cp.async.commit_group;" ::: "memory")
#define CPA_WAIT0()  asm volatile("cp.async.wait_group 0;" ::: "memory")

// ---------------- pre-pass: split Q/K into hi/lo fp16 (Q scaled by log2 e) ----------------
__global__ void split_kernel(const float4* __restrict__ in, int which) {
    __half2* hi = (__half2*)(which ? g_Kh : g_Qh);
    __half2* lo = (__half2*)(which ? g_Kl : g_Ql);
    const float sc = which ? 1.0f : 1.4426950408889634f;
    int n4 = TOT / 4;
    for (int i = blockIdx.x * blockDim.x + threadIdx.x; i < n4; i += gridDim.x * blockDim.x) {
        float4 x = in[i];
        x.x *= sc; x.y *= sc; x.z *= sc; x.w *= sc;
        __half hx = __float2half_rn(x.x), hy = __float2half_rn(x.y);
        __half hz = __float2half_rn(x.z), hw = __float2half_rn(x.w);
        hi[2*i]   = __halves2half2(hx, hy);
        hi[2*i+1] = __halves2half2(hz, hw);
        lo[2*i]   = __floats2half2_rn(x.x - __half2float(hx), x.y - __half2float(hy));
        lo[2*i+1] = __floats2half2_rn(x.z - __half2float(hz), x.w - __half2float(hw));
    }
}

// ---------------- pre-pass: transpose V -> [head][d][l], fp16 (hi only) ----------------
__global__ void vtrans_kernel(const float* __restrict__ V) {
    __shared__ float s[32][33];
    int head = blockIdx.z, lt = blockIdx.x, dt = blockIdx.y;
    const float* base = V + (size_t)head * L_SEQ * DH + (size_t)lt * 32 * DH + dt * 32;
    int t = threadIdx.x;
    int r = t >> 3, c4 = t & 7;
    float4 v = *(const float4*)(base + r * DH + c4 * 4);
    s[r][c4*4+0] = v.x; s[r][c4*4+1] = v.y; s[r][c4*4+2] = v.z; s[r][c4*4+3] = v.w;
    __syncthreads();
    #pragma unroll
    for (int p = 0; p < 2; p++) {
        int idx = t + p * 256;
        int dr = idx >> 4, j = idx & 15;
        float a = s[2*j][dr], b = s[2*j+1][dr];
        size_t o = (size_t)head * DH * L_SEQ + (size_t)(dt*32 + dr) * L_SEQ + lt*32 + 2*j;
        *(__half2*)(g_VTh + o) = __floats2half2_rn(a, b);
    }
}

// ---------------- main attention kernel ----------------
__global__ __launch_bounds__(NTH, 1)
void fa_mma_kernel(float* __restrict__ O) {
    extern __shared__ char smp[];
    const uint32_t sb = smem_u32(smp);

    const int tid = threadIdx.x, wid = tid >> 5, lane = tid & 31;
    const int head = blockIdx.y, q0 = blockIdx.x * BM;
    const size_t hb = (size_t)head * L_SEQ * DH;

    const __half* khg = g_Kh + hb;
    const __half* klg = g_Kl + hb;
    const __half* vhg = g_VTh + (size_t)head * DH * L_SEQ;

    // ---- prefetch tile 0 into buffer 0 ----
    {
        #pragma unroll
        for (int i = 0; i < 8; i++) {
            int idx = tid + i * NTH;
            int arr = idx >> 10, rem = idx & 1023;
            int r = rem >> 4, c = rem & 15;
            cpa16(sb + KBUF0 + (arr ? KL_OFF : 0u) + r * QSTR + c * 16,
                  (arr ? klg : khg) + (size_t)r * DH + c * 8);
        }
        #pragma unroll
        for (int i = 0; i < 4; i++) {
            int idx = tid + i * NTH;
            int r = idx >> 3, c = idx & 7;
            cpa16(sb + VBUF0 + r * VSTR + c * 16,
                  vhg + (size_t)r * L_SEQ + c * 8);
        }
        CPA_COMMIT();
    }

    // ---- load Q tile (plain LDG/STS, once) ----
    {
        const __half* qh = g_Qh + hb + (size_t)q0 * DH;
        const __half* ql = g_Ql + hb + (size_t)q0 * DH;
        #pragma unroll
        for (int i = 0; i < 16; i++) {
            int idx = tid + i * NTH;
            int arr = idx >> 11, rem = idx & 2047;
            int r = rem >> 4, c = rem & 15;
            uint4 v = *(const uint4*)((arr ? ql : qh) + r * DH + c * 8);
            *(uint4*)(smp + (arr ? SQL : SQH) + r * QSTR + c * 16) = v;
        }
    }

    // ldmatrix lane addressing
    const int qrow = (wid * 16) + (lane & 7) + ((lane >> 3) & 1) * 8;
    const uint32_t qcol = ((lane >> 4) & 1) * 16;
    const uint32_t qaH = sb + SQH + qrow * QSTR + qcol;
    const uint32_t qaL = sb + SQL + qrow * QSTR + qcol;
    const int brow = (lane & 7) + ((lane >> 4) & 1) * 8;
    const uint32_t bcolb = ((lane >> 3) & 1) * 16;
    const uint32_t kfrag = brow * QSTR + bcolb;    // + K buffer base (+KL_OFF for lo)
    const uint32_t vfrag = brow * VSTR + bcolb;    // + V buffer base

    float oc[16][4];
    #pragma unroll
    for (int i = 0; i < 16; i++)
        #pragma unroll
        for (int j = 0; j < 4; j++) oc[i][j] = 0.0f;
    float psum0 = 0.0f, psum1 = 0.0f;
    float m0 = -1e30f, m1 = -1e30f;     // running row max (log2 domain)

    #pragma unroll 1
    for (int t = 0; t < NTILES; t++) {
        CPA_WAIT0();
        __syncthreads();   // tile t data visible; buf[t&1] reads from t-2 done

        // ---- prefetch tile t+1 into the other buffer ----
        if (t + 1 < NTILES) {
            const uint32_t kb = sb + KBUF0 + ((t + 1) & 1) * KBUFSZ;
            const uint32_t vb = sb + VBUF0 + ((t + 1) & 1) * VBUFSZ;
            const size_t ko = (size_t)(t + 1) * BN * DH;
            const int vo = (t + 1) * BN;
            #pragma unroll
            for (int i = 0; i < 8; i++) {
                int idx = tid + i * NTH;
                int arr = idx >> 10, rem = idx & 1023;
                int r = rem >> 4, c = rem & 15;
                cpa16(kb + (arr ? KL_OFF : 0u) + r * QSTR + c * 16,
                      (arr ? klg : khg) + ko + (size_t)r * DH + c * 8);
            }
            #pragma unroll
            for (int i = 0; i < 4; i++) {
                int idx = tid + i * NTH;
                int r = idx >> 3, c = idx & 7;
                cpa16(vb + r * VSTR + c * 16,
                      vhg + (size_t)r * L_SEQ + vo + c * 8);
            }
        }
        CPA_COMMIT();

        const uint32_t kbH = sb + KBUF0 + (t & 1) * KBUFSZ + kfrag;
        const uint32_t kbL = kbH + KL_OFF;
        const uint32_t vbH = sb + VBUF0 + (t & 1) * VBUFSZ + vfrag;

        // ---- S = Qh*Kh + Qh*Kl + Ql*Kh (log2-domain logits) ----
        float sc[8][4];
        #pragma unroll
        for (int i = 0; i < 8; i++)
            #pragma unroll
            for (int j = 0; j < 4; j++) sc[i][j] = 0.0f;

        #pragma unroll
        for (int kk = 0; kk < 8; kk++) {
            uint32_t aH[4], aL[4];
            ldsm4(aH, qaH + kk * 32);
            ldsm4(aL, qaL + kk * 32);
            #pragma unroll
            for (int np = 0; np < 4; np++) {
                uint32_t bH[4], bL[4];
                ldsm4(bH, kbH + np * (16 * QSTR) + kk * 32);
                ldsm4(bL, kbL + np * (16 * QSTR) + kk * 32);
                mma16816(sc[np*2],   aH, bH[0], bH[1]);
                mma16816(sc[np*2],   aH, bL[0], bL[1]);
                mma16816(sc[np*2],   aL, bH[0], bH[1]);
                mma16816(sc[np*2+1], aH, bH[2], bH[3]);
                mma16816(sc[np*2+1], aH, bL[2], bL[3]);
                mma16816(sc[np*2+1], aL, bH[2], bH[3]);
            }
        }

        // ---- online max: row max over this tile, rescale state ----
        float rm0 = -1e30f, rm1 = -1e30f;
        #pragma unroll
        for (int nt = 0; nt < 8; nt++) {
            rm0 = fmaxf(rm0, fmaxf(sc[nt][0], sc[nt][1]));
            rm1 = fmaxf(rm1, fmaxf(sc[nt][2], sc[nt][3]));
        }
        rm0 = fmaxf(rm0, __shfl_xor_sync(0xffffffffu, rm0, 1));
        rm0 = fmaxf(rm0, __shfl_xor_sync(0xffffffffu, rm0, 2));
        rm1 = fmaxf(rm1, __shfl_xor_sync(0xffffffffu, rm1, 1));
        rm1 = fmaxf(rm1, __shfl_xor_sync(0xffffffffu, rm1, 2));
        const float mn0 = fmaxf(m0, rm0), mn1 = fmaxf(m1, rm1);
        const float f0 = ex2(m0 - mn0), f1 = ex2(m1 - mn1);
        m0 = mn0; m1 = mn1;
        psum0 *= f0; psum1 *= f1;
        #pragma unroll
        for (int nt = 0; nt < 16; nt++) {
            oc[nt][0] *= f0; oc[nt][1] *= f0;
            oc[nt][2] *= f1; oc[nt][3] *= f1;
        }

        // ---- p = 2^(s-m) in (0,1]; PV: O += (Ph+Pl)*Vh ----
        #pragma unroll
        for (int kk = 0; kk < 4; kk++) {
            float pA[4], pB[4];
            pA[0] = ex2(sc[2*kk][0] - mn0);
            pA[1] = ex2(sc[2*kk][1] - mn0);
            pA[2] = ex2(sc[2*kk][2] - mn1);
            pA[3] = ex2(sc[2*kk][3] - mn1);
            pB[0] = ex2(sc[2*kk+1][0] - mn0);
            pB[1] = ex2(sc[2*kk+1][1] - mn0);
            pB[2] = ex2(sc[2*kk+1][2] - mn1);
            pB[3] = ex2(sc[2*kk+1][3] - mn1);
            psum0 += (pA[0] + pA[1]) + (pB[0] + pB[1]);
            psum1 += (pA[2] + pA[3]) + (pB[2] + pB[3]);

            uint32_t aPh[4], aPl[4];
            aPh[0] = packh2(pA[0], pA[1]);
            aPh[1] = packh2(pA[2], pA[3]);
            aPh[2] = packh2(pB[0], pB[1]);
            aPh[3] = packh2(pB[2], pB[3]);
            {
                __half2 h;
                h = *(__half2*)&aPh[0];
                aPl[0] = packh2(pA[0] - __half2float(h.x), pA[1] - __half2float(h.y));
                h = *(__half2*)&aPh[1];
                aPl[1] = packh2(pA[2] - __half2float(h.x), pA[3] - __half2float(h.y));
                h = *(__half2*)&aPh[2];
                aPl[2] = packh2(pB[0] - __half2float(h.x), pB[1] - __half2float(h.y));
                h = *(__half2*)&aPh[3];
                aPl[3] = packh2(pB[2] - __half2float(h.x), pB[3] - __half2float(h.y));
            }

            #pragma unroll
            for (int np = 0; np < 8; np++) {
                uint32_t bH[4];
                ldsm4(bH, vbH + np * (16 * VSTR) + kk * 32);
                mma16816(oc[np*2],   aPh, bH[0], bH[1]);
                mma16816(oc[np*2],   aPl, bH[0], bH[1]);
                mma16816(oc[np*2+1], aPh, bH[2], bH[3]);
                mma16816(oc[np*2+1], aPl, bH[2], bH[3]);
            }
        }
    }

    // ---- row sums across quad lanes ----
    psum0 += __shfl_xor_sync(0xffffffffu, psum0, 1);
    psum0 += __shfl_xor_sync(0xffffffffu, psum0, 2);
    psum1 += __shfl_xor_sync(0xffffffffu, psum1, 1);
    psum1 += __shfl_xor_sync(0xffffffffu, psum1, 2);
    float inv0 = 1.0f / psum0, inv1 = 1.0f / psum1;

    // ---- write O ----
    const int r0 = q0 + wid * 16 + (lane >> 2);
    const int cb = (lane & 3) * 2;
    float* Op0 = O + hb + (size_t)r0 * DH + cb;
    float* Op1 = Op0 + 8 * DH;
    #pragma unroll
    for (int nt = 0; nt < 16; nt++) {
        *(float2*)(Op0 + nt * 8) = make_float2(oc[nt][0] * inv0, oc[nt][1] * inv0);
        *(float2*)(Op1 + nt * 8) = make_float2(oc[nt][2] * inv1, oc[nt][3] * inv1);
    }
}

extern "C" void kernel_launch(void* const* d_in, const int* in_sizes, int n_in,
                              void* d_out, int out_size) {
    const float* Q = (const float*)d_in[0];
    const float* K = (const float*)d_in[1];
    const float* V = (const float*)d_in[2];
    float* O = (float*)d_out;

    split_kernel<<<8192, 256>>>((const float4*)Q, 0);
    split_kernel<<<8192, 256>>>((const float4*)K, 1);
    vtrans_kernel<<<dim3(L_SEQ / 32, DH / 32, NHEADS), 256>>>(V);

    cudaFuncSetAttribute(fa_mma_kernel, cudaFuncAttributeMaxDynamicSharedMemorySize,
                         (int)SMEM_TOTAL);
    fa_mma_kernel<<<dim3(L_SEQ / BM, NHEADS), NTH, SMEM_TOTAL>>>(O);
}

// round 17
// speedup vs baseline: 1.4247x; 1.1742x over previous
#include <cuda_runtime.h>
#include <cuda_fp16.h>
#include <cstdint>

// Flash attention via mma.sync (HMMA fp16), hi/lo split for S, fp32 accum.
// B=4,H=16,L=2048,D=128. scale=1. Q pre-scaled by log2(e).
// Online softmax (log2 domain), p = 2^(s-m) in (0,1] -> fp16-safe.
// PV = Ph*Vh single term (P-lo and V-lo truncation each ~2.1e-4, calibrated).
// cp.async double-buffered K/V.

#define L_SEQ   2048
#define DH      128
#define NHEADS  64
#define BM      128
#define BN      64
#define NTILES  (L_SEQ/BN)
#define NTH     256
#define TOT     (NHEADS*L_SEQ*DH)

__device__ __half g_Qh[TOT], g_Ql[TOT], g_Kh[TOT], g_Kl[TOT];
__device__ __half g_VTh[TOT];   // [head][d][l]

// smem layout (bytes)
#define QSTR 272
#define VSTR 144
#define SQH   0u
#define SQL   34816u
#define KBUF0 69632u          // KH 17408 | KL 17408
#define KBUFSZ 34816u
#define KL_OFF 17408u
#define VBUF0 139264u         // VH only, 18432
#define VBUFSZ 18432u
#define SMEM_TOTAL 176128u

__device__ __forceinline__ uint32_t smem_u32(const void* p) {
    uint32_t a;
    asm("{ .reg .u64 t; cvta.to.shared.u64 t, %1; cvt.u32.u64 %0, t; }" : "=r"(a) : "l"(p));
    return a;
}
__device__ __forceinline__ void ldsm4(uint32_t r[4], uint32_t addr) {
    asm volatile("ldmatrix.sync.aligned.m8n8.x4.shared.b16 {%0,%1,%2,%3}, [%4];"
                 : "=r"(r[0]), "=r"(r[1]), "=r"(r[2]), "=r"(r[3]) : "r"(addr));
}
__device__ __forceinline__ void mma16816(float c[4], const uint32_t a[4],
                                         uint32_t b0, uint32_t b1) {
    asm volatile("mma.sync.aligned.m16n8k16.row.col.f32.f16.f16.f32 "
                 "{%0,%1,%2,%3},{%4,%5,%6,%7},{%8,%9},{%0,%1,%2,%3};"
                 : "+f"(c[0]), "+f"(c[1]), "+f"(c[2]), "+f"(c[3])
                 : "r"(a[0]), "r"(a[1]), "r"(a[2]), "r"(a[3]), "r"(b0), "r"(b1));
}
__device__ __forceinline__ uint32_t packh2(float x, float y) {
    __half2 t = __floats2half2_rn(x, y);
    return *reinterpret_cast<uint32_t*>(&t);
}
__device__ __forceinline__ float ex2(float x) {
    float y; asm("ex2.approx.f32 %0, %1;" : "=f"(y) : "f"(x)); return y;
}
__device__ __forceinline__ void cpa16(uint32_t dst, const void* src) {
    asm volatile("cp.async.cg.shared.global [%0], [%1], 16;" :: "r"(dst), "l"(src));
}
#define CPA_COMMIT() asm volatile("cp.async.commit_group;" ::: "memory")
#define CPA_WAIT0()  asm volatile("cp.async.wait_group 0;" ::: "memory")

// ---------------- pre-pass: split Q/K into hi/lo fp16 (Q scaled by log2 e) ----------------
__global__ void split_kernel(const float4* __restrict__ in, int which) {
    __half2* hi = (__half2*)(which ? g_Kh : g_Qh);
    __half2* lo = (__half2*)(which ? g_Kl : g_Ql);
    const float sc = which ? 1.0f : 1.4426950408889634f;
    int n4 = TOT / 4;
    for (int i = blockIdx.x * blockDim.x + threadIdx.x; i < n4; i += gridDim.x * blockDim.x) {
        float4 x = in[i];
        x.x *= sc; x.y *= sc; x.z *= sc; x.w *= sc;
        __half hx = __float2half_rn(x.x), hy = __float2half_rn(x.y);
        __half hz = __float2half_rn(x.z), hw = __float2half_rn(x.w);
        hi[2*i]   = __halves2half2(hx, hy);
        hi[2*i+1] = __halves2half2(hz, hw);
        lo[2*i]   = __floats2half2_rn(x.x - __half2float(hx), x.y - __half2float(hy));
        lo[2*i+1] = __floats2half2_rn(x.z - __half2float(hz), x.w - __half2float(hw));
    }
}

// ---------------- pre-pass: transpose V -> [head][d][l], fp16 (hi only) ----------------
__global__ void vtrans_kernel(const float* __restrict__ V) {
    __shared__ float s[32][33];
    int head = blockIdx.z, lt = blockIdx.x, dt = blockIdx.y;
    const float* base = V + (size_t)head * L_SEQ * DH + (size_t)lt * 32 * DH + dt * 32;
    int t = threadIdx.x;
    int r = t >> 3, c4 = t & 7;
    float4 v = *(const float4*)(base + r * DH + c4 * 4);
    s[r][c4*4+0] = v.x; s[r][c4*4+1] = v.y; s[r][c4*4+2] = v.z; s[r][c4*4+3] = v.w;
    __syncthreads();
    #pragma unroll
    for (int p = 0; p < 2; p++) {
        int idx = t + p * 256;
        int dr = idx >> 4, j = idx & 15;
        float a = s[2*j][dr], b = s[2*j+1][dr];
        size_t o = (size_t)head * DH * L_SEQ + (size_t)(dt*32 + dr) * L_SEQ + lt*32 + 2*j;
        *(__half2*)(g_VTh + o) = __floats2half2_rn(a, b);
    }
}

// ---------------- main attention kernel ----------------
__global__ __launch_bounds__(NTH, 1)
void fa_mma_kernel(float* __restrict__ O) {
    extern __shared__ char smp[];
    const uint32_t sb = smem_u32(smp);

    const int tid = threadIdx.x, wid = tid >> 5, lane = tid & 31;
    const int head = blockIdx.y, q0 = blockIdx.x * BM;
    const size_t hb = (size_t)head * L_SEQ * DH;

    const __half* khg = g_Kh + hb;
    const __half* klg = g_Kl + hb;
    const __half* vhg = g_VTh + (size_t)head * DH * L_SEQ;

    // ---- prefetch tile 0 into buffer 0 ----
    {
        #pragma unroll
        for (int i = 0; i < 8; i++) {
            int idx = tid + i * NTH;
            int arr = idx >> 10, rem = idx & 1023;
            int r = rem >> 4, c = rem & 15;
            cpa16(sb + KBUF0 + (arr ? KL_OFF : 0u) + r * QSTR + c * 16,
                  (arr ? klg : khg) + (size_t)r * DH + c * 8);
        }
        #pragma unroll
        for (int i = 0; i < 4; i++) {
            int idx = tid + i * NTH;
            int r = idx >> 3, c = idx & 7;
            cpa16(sb + VBUF0 + r * VSTR + c * 16,
                  vhg + (size_t)r * L_SEQ + c * 8);
        }
        CPA_COMMIT();
    }

    // ---- load Q tile (plain LDG/STS, once) ----
    {
        const __half* qh = g_Qh + hb + (size_t)q0 * DH;
        const __half* ql = g_Ql + hb + (size_t)q0 * DH;
        #pragma unroll
        for (int i = 0; i < 16; i++) {
            int idx = tid + i * NTH;
            int arr = idx >> 11, rem = idx & 2047;
            int r = rem >> 4, c = rem & 15;
            uint4 v = *(const uint4*)((arr ? ql : qh) + r * DH + c * 8);
            *(uint4*)(smp + (arr ? SQL : SQH) + r * QSTR + c * 16) = v;
        }
    }

    // ldmatrix lane addressing
    const int qrow = (wid * 16) + (lane & 7) + ((lane >> 3) & 1) * 8;
    const uint32_t qcol = ((lane >> 4) & 1) * 16;
    const uint32_t qaH = sb + SQH + qrow * QSTR + qcol;
    const uint32_t qaL = sb + SQL + qrow * QSTR + qcol;
    const int brow = (lane & 7) + ((lane >> 4) & 1) * 8;
    const uint32_t bcolb = ((lane >> 3) & 1) * 16;
    const uint32_t kfrag = brow * QSTR + bcolb;    // + K buffer base (+KL_OFF for lo)
    const uint32_t vfrag = brow * VSTR + bcolb;    // + V buffer base

    float oc[16][4];
    #pragma unroll
    for (int i = 0; i < 16; i++)
        #pragma unroll
        for (int j = 0; j < 4; j++) oc[i][j] = 0.0f;
    float psum0 = 0.0f, psum1 = 0.0f;
    float m0 = -1e30f, m1 = -1e30f;     // running row max (log2 domain)

    #pragma unroll 1
    for (int t = 0; t < NTILES; t++) {
        CPA_WAIT0();
        __syncthreads();   // tile t data visible; buf[t&1] reads from t-2 done

        // ---- prefetch tile t+1 into the other buffer ----
        if (t + 1 < NTILES) {
            const uint32_t kb = sb + KBUF0 + ((t + 1) & 1) * KBUFSZ;
            const uint32_t vb = sb + VBUF0 + ((t + 1) & 1) * VBUFSZ;
            const size_t ko = (size_t)(t + 1) * BN * DH;
            const int vo = (t + 1) * BN;
            #pragma unroll
            for (int i = 0; i < 8; i++) {
                int idx = tid + i * NTH;
                int arr = idx >> 10, rem = idx & 1023;
                int r = rem >> 4, c = rem & 15;
                cpa16(kb + (arr ? KL_OFF : 0u) + r * QSTR + c * 16,
                      (arr ? klg : khg) + ko + (size_t)r * DH + c * 8);
            }
            #pragma unroll
            for (int i = 0; i < 4; i++) {
                int idx = tid + i * NTH;
                int r = idx >> 3, c = idx & 7;
                cpa16(vb + r * VSTR + c * 16,
                      vhg + (size_t)r * L_SEQ + vo + c * 8);
            }
        }
        CPA_COMMIT();

        const uint32_t kbH = sb + KBUF0 + (t & 1) * KBUFSZ + kfrag;
        const uint32_t kbL = kbH + KL_OFF;
        const uint32_t vbH = sb + VBUF0 + (t & 1) * VBUFSZ + vfrag;

        // ---- S = Qh*Kh + Qh*Kl + Ql*Kh (log2-domain logits) ----
        float sc[8][4];
        #pragma unroll
        for (int i = 0; i < 8; i++)
            #pragma unroll
            for (int j = 0; j < 4; j++) sc[i][j] = 0.0f;

        #pragma unroll
        for (int kk = 0; kk < 8; kk++) {
            uint32_t aH[4], aL[4];
            ldsm4(aH, qaH + kk * 32);
            ldsm4(aL, qaL + kk * 32);
            #pragma unroll
            for (int np = 0; np < 4; np++) {
                uint32_t bH[4], bL[4];
                ldsm4(bH, kbH + np * (16 * QSTR) + kk * 32);
                ldsm4(bL, kbL + np * (16 * QSTR) + kk * 32);
                mma16816(sc[np*2],   aH, bH[0], bH[1]);
                mma16816(sc[np*2],   aH, bL[0], bL[1]);
                mma16816(sc[np*2],   aL, bH[0], bH[1]);
                mma16816(sc[np*2+1], aH, bH[2], bH[3]);
                mma16816(sc[np*2+1], aH, bL[2], bL[3]);
                mma16816(sc[np*2+1], aL, bH[2], bH[3]);
            }
        }

        // ---- online max: row max over this tile, rescale state ----
        float rm0 = -1e30f, rm1 = -1e30f;
        #pragma unroll
        for (int nt = 0; nt < 8; nt++) {
            rm0 = fmaxf(rm0, fmaxf(sc[nt][0], sc[nt][1]));
            rm1 = fmaxf(rm1, fmaxf(sc[nt][2], sc[nt][3]));
        }
        rm0 = fmaxf(rm0, __shfl_xor_sync(0xffffffffu, rm0, 1));
        rm0 = fmaxf(rm0, __shfl_xor_sync(0xffffffffu, rm0, 2));
        rm1 = fmaxf(rm1, __shfl_xor_sync(0xffffffffu, rm1, 1));
        rm1 = fmaxf(rm1, __shfl_xor_sync(0xffffffffu, rm1, 2));
        const float mn0 = fmaxf(m0, rm0), mn1 = fmaxf(m1, rm1);
        const float f0 = ex2(m0 - mn0), f1 = ex2(m1 - mn1);
        m0 = mn0; m1 = mn1;
        psum0 *= f0; psum1 *= f1;
        #pragma unroll
        for (int nt = 0; nt < 16; nt++) {
            oc[nt][0] *= f0; oc[nt][1] *= f0;
            oc[nt][2] *= f1; oc[nt][3] *= f1;
        }

        // ---- p = 2^(s-m) in (0,1]; PV: O += Ph*Vh ----
        #pragma unroll
        for (int kk = 0; kk < 4; kk++) {
            float pA[4], pB[4];
            pA[0] = ex2(sc[2*kk][0] - mn0);
            pA[1] = ex2(sc[2*kk][1] - mn0);
            pA[2] = ex2(sc[2*kk][2] - mn1);
            pA[3] = ex2(sc[2*kk][3] - mn1);
            pB[0] = ex2(sc[2*kk+1][0] - mn0);
            pB[1] = ex2(sc[2*kk+1][1] - mn0);
            pB[2] = ex2(sc[2*kk+1][2] - mn1);
            pB[3] = ex2(sc[2*kk+1][3] - mn1);
            psum0 += (pA[0] + pA[1]) + (pB[0] + pB[1]);
            psum1 += (pA[2] + pA[3]) + (pB[2] + pB[3]);

            uint32_t aPh[4];
            aPh[0] = packh2(pA[0], pA[1]);
            aPh[1] = packh2(pA[2], pA[3]);
            aPh[2] = packh2(pB[0], pB[1]);
            aPh[3] = packh2(pB[2], pB[3]);

            #pragma unroll
            for (int np = 0; np < 8; np++) {
                uint32_t bH[4];
                ldsm4(bH, vbH + np * (16 * VSTR) + kk * 32);
                mma16816(oc[np*2],   aPh, bH[0], bH[1]);
                mma16816(oc[np*2+1], aPh, bH[2], bH[3]);
            }
        }
    }

    // ---- row sums across quad lanes ----
    psum0 += __shfl_xor_sync(0xffffffffu, psum0, 1);
    psum0 += __shfl_xor_sync(0xffffffffu, psum0, 2);
    psum1 += __shfl_xor_sync(0xffffffffu, psum1, 1);
    psum1 += __shfl_xor_sync(0xffffffffu, psum1, 2);
    float inv0 = 1.0f / psum0, inv1 = 1.0f / psum1;

    // ---- write O ----
    const int r0 = q0 + wid * 16 + (lane >> 2);
    const int cb = (lane & 3) * 2;
    float* Op0 = O + hb + (size_t)r0 * DH + cb;
    float* Op1 = Op0 + 8 * DH;
    #pragma unroll
    for (int nt = 0; nt < 16; nt++) {
        *(float2*)(Op0 + nt * 8) = make_float2(oc[nt][0] * inv0, oc[nt][1] * inv0);
        *(float2*)(Op1 + nt * 8) = make_float2(oc[nt][2] * inv1, oc[nt][3] * inv1);
    }
}

extern "C" void kernel_launch(void* const* d_in, const int* in_sizes, int n_in,
                              void* d_out, int out_size) {
    const float* Q = (const float*)d_in[0];
    const float* K = (const float*)d_in[1];
    const float* V = (const float*)d_in[2];
    float* O = (float*)d_out;

    split_kernel<<<8192, 256>>>((const float4*)Q, 0);
    split_kernel<<<8192, 256>>>((const float4*)K, 1);
    vtrans_kernel<<<dim3(L_SEQ / 32, DH / 32, NHEADS), 256>>>(V);

    cudaFuncSetAttribute(fa_mma_kernel, cudaFuncAttributeMaxDynamicSharedMemorySize,
                         (int)SMEM_TOTAL);
    fa_mma_kernel<<<dim3(L_SEQ / BM, NHEADS), NTH, SMEM_TOTAL>>>(O);
}